// round 12
// baseline (speedup 1.0000x reference)
#include <cuda_runtime.h>
#include <cuda_bf16.h>
#include <math.h>
#include <stdint.h>

#define NN 100000
#define EE 1600000
#define DD 128
#define CC 47
#define PRW 96   // [P(47) | R(47) | pad(2)] width for layer 2

// ==================== scratch (device globals, no allocation) ====================
__device__ int   g_deg[NN];
__device__ int   g_rowstart[NN + 1];
__device__ int   g_cursor[NN];
__device__ int   g_csrsrc[EE];
__device__ float g_agg[(size_t)NN * DD];
__device__ float g_b0[(size_t)NN * DD];
__device__ float g_b1[(size_t)NN * DD];
__device__ float g_pr[(size_t)NN * PRW];
__device__ float g_stats[2 * DD];
__device__ float g_scale[DD];
__device__ float g_shift[DD];
__device__ int   g_is64;
// W^T images, bf16 hi/lo: layers 0/1: [128 n][256 k]; layer 2: [96 n][128 k]
__device__ __nv_bfloat16 g_w01hi[2][128 * 256];
__device__ __nv_bfloat16 g_w01lo[2][128 * 256];
__device__ __nv_bfloat16 g_w2hi[PRW * 128];
__device__ __nv_bfloat16 g_w2lo[PRW * 128];

#define SCAN_B 1024
#define SCAN_NB ((NN + SCAN_B - 1) / SCAN_B)
__device__ int g_bsum[SCAN_NB];

// ==================== PTX helpers (baseline ISA, no 'a' features) ====================
static __device__ __forceinline__ uint32_t smem_u32(const void* p) {
    uint32_t a;
    asm("{ .reg .u64 t; cvta.to.shared.u64 t, %1; cvt.u32.u64 %0, t; }" : "=r"(a) : "l"(p));
    return a;
}
#define LDSM4(r, a) \
    asm volatile("ldmatrix.sync.aligned.m8n8.x4.shared.b16 {%0,%1,%2,%3}, [%4];" \
                 : "=r"((r)[0]), "=r"((r)[1]), "=r"((r)[2]), "=r"((r)[3]) : "r"(a))
#define MMA16816(d, a, b0, b1) \
    asm volatile("mma.sync.aligned.m16n8k16.row.col.f32.bf16.bf16.f32 " \
                 "{%0,%1,%2,%3}, {%4,%5,%6,%7}, {%8,%9}, {%0,%1,%2,%3};" \
                 : "+f"((d)[0]), "+f"((d)[1]), "+f"((d)[2]), "+f"((d)[3]) \
                 : "r"((a)[0]), "r"((a)[1]), "r"((a)[2]), "r"((a)[3]), "r"(b0), "r"(b1))

// ==================== edge dtype probe ====================
__global__ void probe_kernel(const int* __restrict__ ei32) {
    if (threadIdx.x == 0) {
        int nz = 0;
        for (int i = 0; i < 512; i++) nz += (ei32[2 * i + 1] != 0);
        g_is64 = (nz == 0) ? 1 : 0;
    }
}
__device__ __forceinline__ int edge_val(const void* ei, int is64, size_t idx) {
    if (is64) return (int)((const long long*)ei)[idx];
    return ((const int*)ei)[idx];
}

// ==================== CSR build ====================
__global__ void zero_deg_kernel() {
    int i = blockIdx.x * blockDim.x + threadIdx.x;
    if (i < NN) g_deg[i] = 0;
    if (i < 2 * DD) g_stats[i] = 0.f;
}
__global__ void deg_kernel(const void* __restrict__ ei) {
    int e = blockIdx.x * blockDim.x + threadIdx.x;
    int is64 = g_is64;
    if (e < EE) atomicAdd(&g_deg[edge_val(ei, is64, (size_t)EE + e)], 1);
}
__global__ void blocksum_kernel() {
    __shared__ int ws[32];
    int i = blockIdx.x * SCAN_B + threadIdx.x;
    int v = (i < NN) ? g_deg[i] : 0;
#pragma unroll
    for (int o = 16; o; o >>= 1) v += __shfl_xor_sync(0xffffffffu, v, o);
    if ((threadIdx.x & 31) == 0) ws[threadIdx.x >> 5] = v;
    __syncthreads();
    if (threadIdx.x < 32) {
        int s = ws[threadIdx.x];
#pragma unroll
        for (int o = 16; o; o >>= 1) s += __shfl_xor_sync(0xffffffffu, s, o);
        if (threadIdx.x == 0) g_bsum[blockIdx.x] = s;
    }
}
__global__ void scanbsum_kernel() {
    __shared__ int sm[128];
    int t = threadIdx.x;
    int v = (t < SCAN_NB) ? g_bsum[t] : 0;
    sm[t] = v;
    __syncthreads();
#pragma unroll
    for (int o = 1; o < 128; o <<= 1) {
        int x = (t >= o) ? sm[t - o] : 0;
        __syncthreads();
        sm[t] += x;
        __syncthreads();
    }
    if (t < SCAN_NB) g_bsum[t] = sm[t] - v;
}
__global__ void scanfinal_kernel() {
    __shared__ int wsum[32];
    int t = threadIdx.x;
    int lane = t & 31, wid = t >> 5;
    int i = blockIdx.x * SCAN_B + t;
    int v = (i < NN) ? g_deg[i] : 0;
    int x = v;
#pragma unroll
    for (int o = 1; o < 32; o <<= 1) {
        int u = __shfl_up_sync(0xffffffffu, x, o);
        if (lane >= o) x += u;
    }
    if (lane == 31) wsum[wid] = x;
    __syncthreads();
    if (wid == 0) {
        int s = wsum[lane];
        int y = s;
#pragma unroll
        for (int o = 1; o < 32; o <<= 1) {
            int u = __shfl_up_sync(0xffffffffu, y, o);
            if (lane >= o) y += u;
        }
        wsum[lane] = y - s;
    }
    __syncthreads();
    int excl = x - v + wsum[wid] + g_bsum[blockIdx.x];
    if (i < NN) {
        g_rowstart[i] = excl;
        g_cursor[i] = excl;
    }
    if (i == NN - 1) g_rowstart[NN] = EE;
}
__global__ void scatter_kernel(const void* __restrict__ ei) {
    int e = blockIdx.x * blockDim.x + threadIdx.x;
    int is64 = g_is64;
    if (e < EE) {
        int d = edge_val(ei, is64, (size_t)EE + e);
        int s = edge_val(ei, is64, (size_t)e);
        int p = atomicAdd(&g_cursor[d], 1);
        g_csrsrc[p] = s;
    }
}

// ==================== weight conversion: fp32 -> W^T bf16 hi/lo ====================
__global__ void conv_w01_kernel(const float* __restrict__ Wl0, const float* __restrict__ Wr0,
                                const float* __restrict__ Wl1, const float* __restrict__ Wr1) {
    int idx = blockIdx.x * blockDim.x + threadIdx.x;
    if (idx >= 2 * 128 * 256) return;
    int layer = idx >> 15;
    int r = idx & 32767;
    int n = r >> 8;
    int k = r & 255;
    const float* Wl = layer ? Wl1 : Wl0;
    const float* Wr = layer ? Wr1 : Wr0;
    float v = (k < 128) ? Wl[k * 128 + n] : Wr[(k - 128) * 128 + n];
    __nv_bfloat16 hi = __float2bfloat16_rn(v);
    __nv_bfloat16 lo = __float2bfloat16_rn(v - __bfloat162float(hi));
    g_w01hi[layer][n * 256 + k] = hi;
    g_w01lo[layer][n * 256 + k] = lo;
}
__global__ void conv_w2_kernel(const float* __restrict__ Wl2, const float* __restrict__ Wr2) {
    int idx = blockIdx.x * blockDim.x + threadIdx.x;
    if (idx >= PRW * 128) return;
    int n = idx >> 7;
    int k = idx & 127;
    float v = 0.f;
    if (n < CC) v = Wl2[k * CC + n];
    else if (n < 2 * CC) v = Wr2[k * CC + (n - CC)];
    __nv_bfloat16 hi = __float2bfloat16_rn(v);
    __nv_bfloat16 lo = __float2bfloat16_rn(v - __bfloat162float(hi));
    g_w2hi[n * 128 + k] = hi;
    g_w2lo[n * 128 + k] = lo;
}

// ==================== BN finalize: stats -> scale/shift tables, re-zero stats ====================
__global__ void finalize_kernel(const float* __restrict__ g, const float* __restrict__ b) {
    int c = threadIdx.x;
    if (c < DD) {
        float mu = g_stats[c] * (1.0f / NN);
        float var = g_stats[DD + c] * (1.0f / NN) - mu * mu;
        float sc = rsqrtf(var + 1e-5f) * g[c];
        g_scale[c] = sc;
        g_shift[c] = b[c] - mu * sc;
        g_stats[c] = 0.f;
        g_stats[DD + c] = 0.f;
    }
}

// ==================== mean aggregation (warp per node, optional fused BN+ReLU) ====================
template <bool APPLY>
__global__ void agg_kernel(const float* __restrict__ X, float* __restrict__ AGG) {
    int warp = (blockIdx.x * blockDim.x + threadIdx.x) >> 5;
    int lane = threadIdx.x & 31;
    if (warp >= NN) return;
    float4 s4, h4;
    if (APPLY) {
        s4 = *reinterpret_cast<const float4*>(g_scale + lane * 4);
        h4 = *reinterpret_cast<const float4*>(g_shift + lane * 4);
    }
    int beg = g_rowstart[warp];
    int end = g_rowstart[warp + 1];
    float4 acc = make_float4(0.f, 0.f, 0.f, 0.f);
    for (int e = beg; e < end; e++) {
        int s = g_csrsrc[e];
        float4 v = *reinterpret_cast<const float4*>(X + (size_t)s * DD + lane * 4);
        if (APPLY) {
            v.x = fmaxf(fmaf(v.x, s4.x, h4.x), 0.f);
            v.y = fmaxf(fmaf(v.y, s4.y, h4.y), 0.f);
            v.z = fmaxf(fmaf(v.z, s4.z, h4.z), 0.f);
            v.w = fmaxf(fmaf(v.w, s4.w, h4.w), 0.f);
        }
        acc.x += v.x; acc.y += v.y; acc.z += v.z; acc.w += v.w;
    }
    int cnt = end - beg;
    float inv = 1.0f / (float)(cnt > 0 ? cnt : 1);
    acc.x *= inv; acc.y *= inv; acc.z *= inv; acc.w *= inv;
    *reinterpret_cast<float4*>(AGG + (size_t)warp * DD + lane * 4) = acc;
}

// ==================== HMMA split-bf16 GEMM with fused BN-load + stats epilogue ====================
#define STRIDE_B 272
template <int NT, int NCHUNK, bool APPLY_A0, bool APPLY_A1, bool STATS>
__global__ void __launch_bounds__(256, 1)
gemm_mma(const float* __restrict__ A0, const float* __restrict__ A1,
         const __nv_bfloat16* __restrict__ Whi, const __nv_bfloat16* __restrict__ Wlo,
         const float* __restrict__ bias, float* __restrict__ Y, int ldY) {
    extern __shared__ char smem[];
    constexpr int AHI = 0;
    constexpr int ALO = 128 * STRIDE_B;
    constexpr int WHI = 2 * 128 * STRIDE_B;
    constexpr int WLO = WHI + NT * STRIDE_B;
    constexpr int NB4 = NT / 32;
    constexpr int NTJ = NT / 16;

    const uint32_t sb = smem_u32(smem);
    const int tid = threadIdx.x;
    const int wid = tid >> 5, lane = tid & 31;
    const int warp_m = wid & 3, warp_n = wid >> 2;
    const int nbase = blockIdx.x * 128;

    float acc[2][NTJ][4];
#pragma unroll
    for (int i = 0; i < 2; i++)
#pragma unroll
        for (int j = 0; j < NTJ; j++)
#pragma unroll
            for (int q = 0; q < 4; q++) acc[i][j][q] = 0.f;

    const int lt = lane >> 3, lrow = lane & 7;
    const int a_m = warp_m * 32 + lrow + ((lt & 1) << 3);
    const int a_k = (lt >> 1) << 3;
    const int b_n = warp_n * (NT / 2) + lrow + ((lt >> 1) << 3);
    const int b_k = (lt & 1) << 3;

#pragma unroll 1
    for (int c = 0; c < NCHUNK; c++) {
        const float* Asrc = (NCHUNK == 2 && c == 1) ? A1 : A0;
        const bool apply = (c == 0) ? APPLY_A0 : APPLY_A1;
        for (int i = tid; i < 4096; i += 256) {
            int r = i >> 5, q = i & 31;
            int n = nbase + r;
            if (n >= NN) n = NN - 1;
            float4 v = __ldg(reinterpret_cast<const float4*>(Asrc + (size_t)n * DD) + q);
            if (apply) {
                float4 s4 = *reinterpret_cast<const float4*>(g_scale + q * 4);
                float4 h4 = *reinterpret_cast<const float4*>(g_shift + q * 4);
                v.x = fmaxf(fmaf(v.x, s4.x, h4.x), 0.f);
                v.y = fmaxf(fmaf(v.y, s4.y, h4.y), 0.f);
                v.z = fmaxf(fmaf(v.z, s4.z, h4.z), 0.f);
                v.w = fmaxf(fmaf(v.w, s4.w, h4.w), 0.f);
            }
            __nv_bfloat16 hx = __float2bfloat16_rn(v.x);
            __nv_bfloat16 hy = __float2bfloat16_rn(v.y);
            __nv_bfloat16 hz = __float2bfloat16_rn(v.z);
            __nv_bfloat16 hw = __float2bfloat16_rn(v.w);
            __nv_bfloat16 lx = __float2bfloat16_rn(v.x - __bfloat162float(hx));
            __nv_bfloat16 ly = __float2bfloat16_rn(v.y - __bfloat162float(hy));
            __nv_bfloat16 lz = __float2bfloat16_rn(v.z - __bfloat162float(hz));
            __nv_bfloat16 lw = __float2bfloat16_rn(v.w - __bfloat162float(hw));
            uint2 hp, lp;
            hp.x = (uint32_t)__bfloat16_as_ushort(hx) | ((uint32_t)__bfloat16_as_ushort(hy) << 16);
            hp.y = (uint32_t)__bfloat16_as_ushort(hz) | ((uint32_t)__bfloat16_as_ushort(hw) << 16);
            lp.x = (uint32_t)__bfloat16_as_ushort(lx) | ((uint32_t)__bfloat16_as_ushort(ly) << 16);
            lp.y = (uint32_t)__bfloat16_as_ushort(lz) | ((uint32_t)__bfloat16_as_ushort(lw) << 16);
            int off = r * STRIDE_B + q * 8;
            *reinterpret_cast<uint2*>(smem + AHI + off) = hp;
            *reinterpret_cast<uint2*>(smem + ALO + off) = lp;
        }
        for (int i = tid; i < NT * 16; i += 256) {
            int n = i >> 4, u4 = i & 15;
            size_t gofs = (size_t)n * (NCHUNK * 128) + c * 128 + u4 * 8;
            int off = n * STRIDE_B + u4 * 16;
            *reinterpret_cast<uint4*>(smem + WHI + off) =
                *reinterpret_cast<const uint4*>(Whi + gofs);
            *reinterpret_cast<uint4*>(smem + WLO + off) =
                *reinterpret_cast<const uint4*>(Wlo + gofs);
        }
        __syncthreads();

#pragma unroll
        for (int ks = 0; ks < 8; ks++) {
            const int kb = ks * 16;
            uint32_t ahi[2][4], alo[2][4], bhi[NB4][4], blo[NB4][4];
#pragma unroll
            for (int mi = 0; mi < 2; mi++) {
                uint32_t ad = sb + AHI + (a_m + mi * 16) * STRIDE_B + (kb + a_k) * 2;
                LDSM4(ahi[mi], ad);
                LDSM4(alo[mi], ad + (ALO - AHI));
            }
#pragma unroll
            for (int g = 0; g < NB4; g++) {
                uint32_t bd = sb + WHI + (b_n + g * 16) * STRIDE_B + (kb + b_k) * 2;
                LDSM4(bhi[g], bd);
                LDSM4(blo[g], bd + (WLO - WHI));
            }
#pragma unroll
            for (int mi = 0; mi < 2; mi++)
#pragma unroll
                for (int g = 0; g < NB4; g++)
#pragma unroll
                    for (int h = 0; h < 2; h++) {
                        int j = g * 2 + h;
                        MMA16816(acc[mi][j], ahi[mi], bhi[g][h * 2], bhi[g][h * 2 + 1]);
                        MMA16816(acc[mi][j], ahi[mi], blo[g][h * 2], blo[g][h * 2 + 1]);
                        MMA16816(acc[mi][j], alo[mi], bhi[g][h * 2], bhi[g][h * 2 + 1]);
                    }
        }
        __syncthreads();
    }

    // ---- epilogue: bias add + store + (optional) column stats ----
    const int mrow = nbase + warp_m * 32 + (lane >> 2);
#pragma unroll
    for (int j = 0; j < NTJ; j++) {
        int col = warp_n * (NT / 2) + j * 8 + (lane & 3) * 2;
        float bx = bias ? bias[col] : 0.f;
        float by = bias ? bias[col + 1] : 0.f;
        float s0 = 0.f, s1 = 0.f, q0 = 0.f, q1 = 0.f;
#pragma unroll
        for (int mi = 0; mi < 2; mi++) {
            int m0 = mrow + mi * 16;
            if (m0 < NN) {
                float ox = acc[mi][j][0] + bx, oy = acc[mi][j][1] + by;
                *reinterpret_cast<float2*>(Y + (size_t)m0 * ldY + col) = make_float2(ox, oy);
                if (STATS) { s0 += ox; q0 += ox * ox; s1 += oy; q1 += oy * oy; }
            }
            int m1 = m0 + 8;
            if (m1 < NN) {
                float ox = acc[mi][j][2] + bx, oy = acc[mi][j][3] + by;
                *reinterpret_cast<float2*>(Y + (size_t)m1 * ldY + col) = make_float2(ox, oy);
                if (STATS) { s0 += ox; q0 += ox * ox; s1 += oy; q1 += oy * oy; }
            }
        }
        if (STATS) {
#pragma unroll
            for (int o = 4; o < 32; o <<= 1) {
                s0 += __shfl_xor_sync(0xffffffffu, s0, o);
                s1 += __shfl_xor_sync(0xffffffffu, s1, o);
                q0 += __shfl_xor_sync(0xffffffffu, q0, o);
                q1 += __shfl_xor_sync(0xffffffffu, q1, o);
            }
            if ((lane >> 2) == 0) {
                atomicAdd(&g_stats[col], s0);
                atomicAdd(&g_stats[col + 1], s1);
                atomicAdd(&g_stats[DD + col], q0);
                atomicAdd(&g_stats[DD + col + 1], q1);
            }
        }
    }
}

// ==================== fused layer-2 tail: mean-agg(P) + R + bias -> log_softmax ====================
__global__ void agg_lsm_kernel(const float* __restrict__ PR, const float* __restrict__ bl2,
                               float* __restrict__ out) {
    int row = blockIdx.x * 8 + (threadIdx.x >> 5);
    int lane = threadIdx.x & 31;
    if (row >= NN) return;
    int beg = g_rowstart[row];
    int end = g_rowstart[row + 1];
    float s0 = 0.f, s1 = 0.f;
    for (int e = beg; e < end; e++) {
        int src = g_csrsrc[e];
        const float* pr = PR + (size_t)src * PRW;
        if (lane < CC) s0 += pr[lane];
        if (lane + 32 < CC) s1 += pr[lane + 32];
    }
    int cnt = end - beg;
    float inv = 1.0f / (float)(cnt > 0 ? cnt : 1);
    const float* prn = PR + (size_t)row * PRW;
    float v0 = (lane < CC) ? s0 * inv + prn[CC + lane] + bl2[lane] : -INFINITY;
    float v1 = (lane + 32 < CC) ? s1 * inv + prn[CC + lane + 32] + bl2[lane + 32] : -INFINITY;

    float m = fmaxf(v0, v1);
#pragma unroll
    for (int o = 16; o > 0; o >>= 1) m = fmaxf(m, __shfl_xor_sync(0xffffffffu, m, o));
    float s = ((lane < CC) ? expf(v0 - m) : 0.f) + ((lane + 32 < CC) ? expf(v1 - m) : 0.f);
#pragma unroll
    for (int o = 16; o > 0; o >>= 1) s += __shfl_xor_sync(0xffffffffu, s, o);
    float l = m + logf(s);
    float* p = out + (size_t)row * CC;
    if (lane < CC) p[lane] = v0 - l;
    if (lane + 32 < CC) p[lane + 32] = v1 - l;
}

// ==================== launch ====================
extern "C" void kernel_launch(void* const* d_in, const int* in_sizes, int n_in,
                              void* d_out, int out_size) {
    const float* x   = (const float*)d_in[0];
    const void*  ei  = d_in[1];
    const float* Wl0 = (const float*)d_in[2];
    const float* bl0 = (const float*)d_in[3];
    const float* Wr0 = (const float*)d_in[4];
    const float* g0  = (const float*)d_in[5];
    const float* be0 = (const float*)d_in[6];
    const float* Wl1 = (const float*)d_in[7];
    const float* bl1 = (const float*)d_in[8];
    const float* Wr1 = (const float*)d_in[9];
    const float* g1  = (const float*)d_in[10];
    const float* be1 = (const float*)d_in[11];
    const float* Wl2 = (const float*)d_in[12];
    const float* bl2 = (const float*)d_in[13];
    const float* Wr2 = (const float*)d_in[14];
    float* out = (float*)d_out;

    void* p;
    cudaGetSymbolAddress(&p, g_agg);   float* aggp = (float*)p;
    cudaGetSymbolAddress(&p, g_b0);    float* b0p  = (float*)p;
    cudaGetSymbolAddress(&p, g_b1);    float* b1p  = (float*)p;
    cudaGetSymbolAddress(&p, g_pr);    float* prp  = (float*)p;
    cudaGetSymbolAddress(&p, g_w01hi); __nv_bfloat16* w01hi = (__nv_bfloat16*)p;
    cudaGetSymbolAddress(&p, g_w01lo); __nv_bfloat16* w01lo = (__nv_bfloat16*)p;
    cudaGetSymbolAddress(&p, g_w2hi);  __nv_bfloat16* w2hi  = (__nv_bfloat16*)p;
    cudaGetSymbolAddress(&p, g_w2lo);  __nv_bfloat16* w2lo  = (__nv_bfloat16*)p;

    const int SMEM01 = 2 * 128 * STRIDE_B + 2 * 128 * STRIDE_B;
    const int SMEM2  = 2 * 128 * STRIDE_B + 2 * PRW * STRIDE_B;
    cudaFuncSetAttribute((const void*)gemm_mma<128, 2, false, false, true>,
                         cudaFuncAttributeMaxDynamicSharedMemorySize, SMEM01);
    cudaFuncSetAttribute((const void*)gemm_mma<128, 2, false, true, true>,
                         cudaFuncAttributeMaxDynamicSharedMemorySize, SMEM01);
    cudaFuncSetAttribute((const void*)gemm_mma<PRW, 1, true, true, false>,
                         cudaFuncAttributeMaxDynamicSharedMemorySize, SMEM2);

    // edge dtype probe + CSR build (+ stats zero)
    probe_kernel<<<1, 32>>>((const int*)ei);
    zero_deg_kernel<<<(NN + 255) / 256, 256>>>();
    deg_kernel<<<(EE + 255) / 256, 256>>>(ei);
    blocksum_kernel<<<SCAN_NB, SCAN_B>>>();
    scanbsum_kernel<<<1, 128>>>();
    scanfinal_kernel<<<SCAN_NB, SCAN_B>>>();
    scatter_kernel<<<(EE + 255) / 256, 256>>>(ei);

    // weight conversion to W^T bf16 hi/lo
    conv_w01_kernel<<<(2 * 128 * 256 + 255) / 256, 256>>>(Wl0, Wr0, Wl1, Wr1);
    conv_w2_kernel<<<(PRW * 128 + 255) / 256, 256>>>(Wl2, Wr2);

    const int gemm_blocks = (NN + 127) / 128;
    const int agg_blocks = (NN * 32 + 255) / 256;

    // layer 0: Y0 = [agg(x)|x]@W0 + b  (pre-BN), stats fused in epilogue
    agg_kernel<false><<<agg_blocks, 256>>>(x, aggp);
    gemm_mma<128, 2, false, false, true><<<gemm_blocks, 256, SMEM01>>>(
        aggp, x, w01hi, w01lo, bl0, b0p, DD);
    finalize_kernel<<<1, 128>>>(g0, be0);

    // layer 1: agg gathers relu(bn0(Y0)); GEMM chunk-1 applies bn0 to Y0 on load
    agg_kernel<true><<<agg_blocks, 256>>>(b0p, aggp);
    gemm_mma<128, 2, false, true, true><<<gemm_blocks, 256, SMEM01>>>(
        aggp, b0p, w01hi + 128 * 256, w01lo + 128 * 256, bl1, b1p, DD);
    finalize_kernel<<<1, 128>>>(g1, be1);

    // layer 2: PR = relu(bn1(Y1)) @ [Wl2|Wr2|0]; fused agg(P)+R+bias+log_softmax
    gemm_mma<PRW, 1, true, true, false><<<gemm_blocks, 256, SMEM2>>>(
        b1p, b1p, w2hi, w2lo, nullptr, prp, PRW);
    agg_lsm_kernel<<<(NN + 7) / 8, 256>>>(prp, bl2, out);
}

// round 14
// speedup vs baseline: 1.0623x; 1.0623x over previous
#include <cuda_runtime.h>
#include <cuda_bf16.h>
#include <math.h>
#include <stdint.h>

#define NN 100000
#define EE 1600000
#define DD 128
#define CC 47
#define PRW 96   // [P(47) | R(47) | pad(2)] width for layer 2

// ==================== scratch (device globals, no allocation) ====================
__device__ int   g_deg[NN];
__device__ int   g_rowstart[NN];
__device__ int   g_cursor[NN];
__device__ int   g_csrsrc[EE];
__device__ float g_b0[(size_t)NN * DD];    // Y0, later Y1 (pre-BN GEMM outputs)
__device__ float g_b1[(size_t)NN * DD];    // h0 = relu(bn0(Y0)) fp32 (for layer-1 agg)
__device__ float g_pr[(size_t)NN * PRW];
__device__ float g_stats[2 * DD];
__device__ float g_scale[DD];
__device__ float g_shift[DD];
__device__ int   g_is64;
__device__ int   g_blockbase;
// split bf16 activation buffers
__device__ __nv_bfloat16 g_aghi[(size_t)NN * DD];   // agg output split
__device__ __nv_bfloat16 g_aglo[(size_t)NN * DD];
__device__ __nv_bfloat16 g_achi[(size_t)NN * DD];   // x-split -> h0-split -> h1-split
__device__ __nv_bfloat16 g_aclo[(size_t)NN * DD];
// W^T images, bf16 hi/lo
__device__ __nv_bfloat16 g_w01hi[2][128 * 256];
__device__ __nv_bfloat16 g_w01lo[2][128 * 256];
__device__ __nv_bfloat16 g_w2hi[PRW * 128];
__device__ __nv_bfloat16 g_w2lo[PRW * 128];

// ==================== PTX helpers (baseline ISA, no 'a' features) ====================
static __device__ __forceinline__ uint32_t smem_u32(const void* p) {
    uint32_t a;
    asm("{ .reg .u64 t; cvta.to.shared.u64 t, %1; cvt.u32.u64 %0, t; }" : "=r"(a) : "l"(p));
    return a;
}
#define LDSM4(r, a) \
    asm volatile("ldmatrix.sync.aligned.m8n8.x4.shared.b16 {%0,%1,%2,%3}, [%4];" \
                 : "=r"((r)[0]), "=r"((r)[1]), "=r"((r)[2]), "=r"((r)[3]) : "r"(a))
#define MMA16816(d, a, b0, b1) \
    asm volatile("mma.sync.aligned.m16n8k16.row.col.f32.bf16.bf16.f32 " \
                 "{%0,%1,%2,%3}, {%4,%5,%6,%7}, {%8,%9}, {%0,%1,%2,%3};" \
                 : "+f"((d)[0]), "+f"((d)[1]), "+f"((d)[2]), "+f"((d)[3]) \
                 : "r"((a)[0]), "r"((a)[1]), "r"((a)[2]), "r"((a)[3]), "r"(b0), "r"(b1))

__device__ __forceinline__ int edge_val(const void* ei, int is64, size_t idx) {
    if (is64) return (int)((const long long*)ei)[idx];
    return ((const int*)ei)[idx];
}

static __device__ __forceinline__ void split2(float4 v, uint2& hp, uint2& lp) {
    __nv_bfloat16 hx = __float2bfloat16_rn(v.x);
    __nv_bfloat16 hy = __float2bfloat16_rn(v.y);
    __nv_bfloat16 hz = __float2bfloat16_rn(v.z);
    __nv_bfloat16 hw = __float2bfloat16_rn(v.w);
    __nv_bfloat16 lx = __float2bfloat16_rn(v.x - __bfloat162float(hx));
    __nv_bfloat16 ly = __float2bfloat16_rn(v.y - __bfloat162float(hy));
    __nv_bfloat16 lz = __float2bfloat16_rn(v.z - __bfloat162float(hz));
    __nv_bfloat16 lw = __float2bfloat16_rn(v.w - __bfloat162float(hw));
    hp.x = (uint32_t)__bfloat16_as_ushort(hx) | ((uint32_t)__bfloat16_as_ushort(hy) << 16);
    hp.y = (uint32_t)__bfloat16_as_ushort(hz) | ((uint32_t)__bfloat16_as_ushort(hw) << 16);
    lp.x = (uint32_t)__bfloat16_as_ushort(lx) | ((uint32_t)__bfloat16_as_ushort(ly) << 16);
    lp.y = (uint32_t)__bfloat16_as_ushort(lz) | ((uint32_t)__bfloat16_as_ushort(lw) << 16);
}

// ==================== init: probe + zero deg/stats/blockbase ====================
__global__ void initall_kernel(const int* __restrict__ ei32) {
    int i = blockIdx.x * blockDim.x + threadIdx.x;
    if (i < NN) g_deg[i] = 0;
    if (i < 2 * DD) g_stats[i] = 0.f;
    if (i == 0) {
        g_blockbase = 0;
        int nz = 0;
        for (int k = 0; k < 512; k++) nz += (ei32[2 * k + 1] != 0);
        g_is64 = (nz == 0) ? 1 : 0;
    }
}

// ==================== CSR build ====================
__global__ void deg_kernel(const void* __restrict__ ei) {
    int e = blockIdx.x * blockDim.x + threadIdx.x;
    int is64 = g_is64;
    if (e < EE) atomicAdd(&g_deg[edge_val(ei, is64, (size_t)EE + e)], 1);
}

// fused scan: per-block scan + atomic block base (ranges contiguous per node; order-free)
__global__ void scanfused_kernel() {
    __shared__ int wsum[32];
    __shared__ int sbase;
    int t = threadIdx.x;
    int lane = t & 31, wid = t >> 5;
    int i = blockIdx.x * 1024 + t;
    int v = (i < NN) ? g_deg[i] : 0;
    int x = v;
#pragma unroll
    for (int o = 1; o < 32; o <<= 1) {
        int u = __shfl_up_sync(0xffffffffu, x, o);
        if (lane >= o) x += u;
    }
    if (lane == 31) wsum[wid] = x;
    __syncthreads();
    if (wid == 0) {
        int s = wsum[lane];
        int y = s;
#pragma unroll
        for (int o = 1; o < 32; o <<= 1) {
            int u = __shfl_up_sync(0xffffffffu, y, o);
            if (lane >= o) y += u;
        }
        wsum[lane] = y - s;
        if (lane == 31) sbase = atomicAdd(&g_blockbase, y);
    }
    __syncthreads();
    int excl = x - v + wsum[wid] + sbase;
    if (i < NN) {
        g_rowstart[i] = excl;
        g_cursor[i] = excl;
    }
}

__global__ void scatter_kernel(const void* __restrict__ ei) {
    int e = blockIdx.x * blockDim.x + threadIdx.x;
    int is64 = g_is64;
    if (e < EE) {
        int d = edge_val(ei, is64, (size_t)EE + e);
        int s = edge_val(ei, is64, (size_t)e);
        int p = atomicAdd(&g_cursor[d], 1);
        g_csrsrc[p] = s;
    }
}

// ==================== prep: weight conversion + x split (one kernel) ====================
#define XITEMS (NN * DD / 4)
__global__ void prep_kernel(const float* __restrict__ x,
                            const float* __restrict__ Wl0, const float* __restrict__ Wr0,
                            const float* __restrict__ Wl1, const float* __restrict__ Wr1,
                            const float* __restrict__ Wl2, const float* __restrict__ Wr2) {
    int idx = blockIdx.x * blockDim.x + threadIdx.x;
    if (idx < XITEMS) {
        float4 v = __ldg(reinterpret_cast<const float4*>(x) + idx);
        uint2 hp, lp;
        split2(v, hp, lp);
        reinterpret_cast<uint2*>(g_achi)[idx] = hp;
        reinterpret_cast<uint2*>(g_aclo)[idx] = lp;
        return;
    }
    int r = idx - XITEMS;
    if (r < 2 * 128 * 256) {
        int layer = r >> 15;
        int q = r & 32767;
        int n = q >> 8;
        int k = q & 255;
        const float* Wl = layer ? Wl1 : Wl0;
        const float* Wr = layer ? Wr1 : Wr0;
        float v = (k < 128) ? Wl[k * 128 + n] : Wr[(k - 128) * 128 + n];
        __nv_bfloat16 hi = __float2bfloat16_rn(v);
        __nv_bfloat16 lo = __float2bfloat16_rn(v - __bfloat162float(hi));
        g_w01hi[layer][n * 256 + k] = hi;
        g_w01lo[layer][n * 256 + k] = lo;
        return;
    }
    r -= 2 * 128 * 256;
    if (r < PRW * 128) {
        int n = r >> 7;
        int k = r & 127;
        float v = 0.f;
        if (n < CC) v = Wl2[k * CC + n];
        else if (n < 2 * CC) v = Wr2[k * CC + (n - CC)];
        __nv_bfloat16 hi = __float2bfloat16_rn(v);
        __nv_bfloat16 lo = __float2bfloat16_rn(v - __bfloat162float(hi));
        g_w2hi[n * 128 + k] = hi;
        g_w2lo[n * 128 + k] = lo;
    }
}

// ==================== BN finalize: stats -> scale/shift, re-zero stats ====================
__global__ void finalize_kernel(const float* __restrict__ g, const float* __restrict__ b) {
    int c = threadIdx.x;
    if (c < DD) {
        float mu = g_stats[c] * (1.0f / NN);
        float var = g_stats[DD + c] * (1.0f / NN) - mu * mu;
        float sc = rsqrtf(var + 1e-5f) * g[c];
        g_scale[c] = sc;
        g_shift[c] = b[c] - mu * sc;
        g_stats[c] = 0.f;
        g_stats[DD + c] = 0.f;
    }
}

// ==================== bnsplit: Y -> (optional fp32 H) + split bf16 pair ====================
template <bool F32OUT>
__global__ void bnsplit_kernel(const float* __restrict__ Y, float* __restrict__ H) {
    int idx = blockIdx.x * blockDim.x + threadIdx.x;
    if (idx >= XITEMS) return;
    int q = idx & 31;
    float4 v = __ldg(reinterpret_cast<const float4*>(Y) + idx);
    float4 s4 = *reinterpret_cast<const float4*>(g_scale + q * 4);
    float4 h4 = *reinterpret_cast<const float4*>(g_shift + q * 4);
    v.x = fmaxf(fmaf(v.x, s4.x, h4.x), 0.f);
    v.y = fmaxf(fmaf(v.y, s4.y, h4.y), 0.f);
    v.z = fmaxf(fmaf(v.z, s4.z, h4.z), 0.f);
    v.w = fmaxf(fmaf(v.w, s4.w, h4.w), 0.f);
    if (F32OUT) reinterpret_cast<float4*>(H)[idx] = v;
    uint2 hp, lp;
    split2(v, hp, lp);
    reinterpret_cast<uint2*>(g_achi)[idx] = hp;
    reinterpret_cast<uint2*>(g_aclo)[idx] = lp;
}

// ==================== mean aggregation (warp per node), split-bf16 output ====================
__global__ void agg_kernel(const float* __restrict__ X) {
    int warp = (blockIdx.x * blockDim.x + threadIdx.x) >> 5;
    int lane = threadIdx.x & 31;
    if (warp >= NN) return;
    int beg = g_rowstart[warp];
    int cnt = g_deg[warp];
    int end = beg + cnt;
    float4 acc = make_float4(0.f, 0.f, 0.f, 0.f);
    int e = beg;
    for (; e + 4 <= end; e += 4) {
        int s0 = g_csrsrc[e + 0];
        int s1 = g_csrsrc[e + 1];
        int s2 = g_csrsrc[e + 2];
        int s3 = g_csrsrc[e + 3];
        float4 v0 = *reinterpret_cast<const float4*>(X + (size_t)s0 * DD + lane * 4);
        float4 v1 = *reinterpret_cast<const float4*>(X + (size_t)s1 * DD + lane * 4);
        float4 v2 = *reinterpret_cast<const float4*>(X + (size_t)s2 * DD + lane * 4);
        float4 v3 = *reinterpret_cast<const float4*>(X + (size_t)s3 * DD + lane * 4);
        acc.x += (v0.x + v1.x) + (v2.x + v3.x);
        acc.y += (v0.y + v1.y) + (v2.y + v3.y);
        acc.z += (v0.z + v1.z) + (v2.z + v3.z);
        acc.w += (v0.w + v1.w) + (v2.w + v3.w);
    }
    for (; e < end; e++) {
        int s = g_csrsrc[e];
        float4 v = *reinterpret_cast<const float4*>(X + (size_t)s * DD + lane * 4);
        acc.x += v.x; acc.y += v.y; acc.z += v.z; acc.w += v.w;
    }
    float inv = 1.0f / (float)(cnt > 0 ? cnt : 1);
    acc.x *= inv; acc.y *= inv; acc.z *= inv; acc.w *= inv;
    uint2 hp, lp;
    split2(acc, hp, lp);
    reinterpret_cast<uint2*>(g_aghi)[(size_t)warp * 32 + lane] = hp;
    reinterpret_cast<uint2*>(g_aglo)[(size_t)warp * 32 + lane] = lp;
}

// ==================== HMMA split-bf16 GEMM (pre-split A, pure-copy loads) ====================
#define STRIDE_B 272
template <int NT, int NCHUNK, bool STATS>
__global__ void __launch_bounds__(256, 1)
gemm_mma(const __nv_bfloat16* __restrict__ A0hi, const __nv_bfloat16* __restrict__ A0lo,
         const __nv_bfloat16* __restrict__ A1hi, const __nv_bfloat16* __restrict__ A1lo,
         const __nv_bfloat16* __restrict__ Whi, const __nv_bfloat16* __restrict__ Wlo,
         const float* __restrict__ bias, float* __restrict__ Y, int ldY) {
    extern __shared__ char smem[];
    constexpr int AHI = 0;
    constexpr int ALO = 128 * STRIDE_B;
    constexpr int WHI = 2 * 128 * STRIDE_B;
    constexpr int WLO = WHI + NT * STRIDE_B;
    constexpr int NB4 = NT / 32;
    constexpr int NTJ = NT / 16;

    const uint32_t sb = smem_u32(smem);
    const int tid = threadIdx.x;
    const int wid = tid >> 5, lane = tid & 31;
    const int warp_m = wid & 3, warp_n = wid >> 2;
    const int nbase = blockIdx.x * 128;

    float acc[2][NTJ][4];
#pragma unroll
    for (int i = 0; i < 2; i++)
#pragma unroll
        for (int j = 0; j < NTJ; j++)
#pragma unroll
            for (int q = 0; q < 4; q++) acc[i][j][q] = 0.f;

    const int lt = lane >> 3, lrow = lane & 7;
    const int a_m = warp_m * 32 + lrow + ((lt & 1) << 3);
    const int a_k = (lt >> 1) << 3;
    const int b_n = warp_n * (NT / 2) + lrow + ((lt >> 1) << 3);
    const int b_k = (lt & 1) << 3;

#pragma unroll 1
    for (int c = 0; c < NCHUNK; c++) {
        const __nv_bfloat16* Ahi = (NCHUNK == 2 && c == 1) ? A1hi : A0hi;
        const __nv_bfloat16* Alo = (NCHUNK == 2 && c == 1) ? A1lo : A0lo;
        // A: pure uint4 copy of pre-split bf16 (128 rows x 256B each buf)
        for (int i = tid; i < 2048; i += 256) {
            int r = i >> 4, u = i & 15;
            int n = nbase + r;
            if (n >= NN) n = NN - 1;
            uint4 h = __ldg(reinterpret_cast<const uint4*>(Ahi + (size_t)n * DD) + u);
            uint4 l = __ldg(reinterpret_cast<const uint4*>(Alo + (size_t)n * DD) + u);
            int off = r * STRIDE_B + u * 16;
            *reinterpret_cast<uint4*>(smem + AHI + off) = h;
            *reinterpret_cast<uint4*>(smem + ALO + off) = l;
        }
        // W copy
        for (int i = tid; i < NT * 16; i += 256) {
            int n = i >> 4, u4 = i & 15;
            size_t gofs = (size_t)n * (NCHUNK * 128) + c * 128 + u4 * 8;
            int off = n * STRIDE_B + u4 * 16;
            *reinterpret_cast<uint4*>(smem + WHI + off) =
                *reinterpret_cast<const uint4*>(Whi + gofs);
            *reinterpret_cast<uint4*>(smem + WLO + off) =
                *reinterpret_cast<const uint4*>(Wlo + gofs);
        }
        __syncthreads();

#pragma unroll
        for (int ks = 0; ks < 8; ks++) {
            const int kb = ks * 16;
            uint32_t ahi[2][4], alo[2][4], bhi[NB4][4], blo[NB4][4];
#pragma unroll
            for (int mi = 0; mi < 2; mi++) {
                uint32_t ad = sb + AHI + (a_m + mi * 16) * STRIDE_B + (kb + a_k) * 2;
                LDSM4(ahi[mi], ad);
                LDSM4(alo[mi], ad + (ALO - AHI));
            }
#pragma unroll
            for (int g = 0; g < NB4; g++) {
                uint32_t bd = sb + WHI + (b_n + g * 16) * STRIDE_B + (kb + b_k) * 2;
                LDSM4(bhi[g], bd);
                LDSM4(blo[g], bd + (WLO - WHI));
            }
#pragma unroll
            for (int mi = 0; mi < 2; mi++)
#pragma unroll
                for (int g = 0; g < NB4; g++)
#pragma unroll
                    for (int h = 0; h < 2; h++) {
                        int j = g * 2 + h;
                        MMA16816(acc[mi][j], ahi[mi], bhi[g][h * 2], bhi[g][h * 2 + 1]);
                        MMA16816(acc[mi][j], ahi[mi], blo[g][h * 2], blo[g][h * 2 + 1]);
                        MMA16816(acc[mi][j], alo[mi], bhi[g][h * 2], bhi[g][h * 2 + 1]);
                    }
        }
        __syncthreads();
    }

    // ---- epilogue: bias + store + optional column stats ----
    const int mrow = nbase + warp_m * 32 + (lane >> 2);
#pragma unroll
    for (int j = 0; j < NTJ; j++) {
        int col = warp_n * (NT / 2) + j * 8 + (lane & 3) * 2;
        float bx = bias ? bias[col] : 0.f;
        float by = bias ? bias[col + 1] : 0.f;
        float s0 = 0.f, s1 = 0.f, q0 = 0.f, q1 = 0.f;
#pragma unroll
        for (int mi = 0; mi < 2; mi++) {
            int m0 = mrow + mi * 16;
            if (m0 < NN) {
                float ox = acc[mi][j][0] + bx, oy = acc[mi][j][1] + by;
                *reinterpret_cast<float2*>(Y + (size_t)m0 * ldY + col) = make_float2(ox, oy);
                if (STATS) { s0 += ox; q0 += ox * ox; s1 += oy; q1 += oy * oy; }
            }
            int m1 = m0 + 8;
            if (m1 < NN) {
                float ox = acc[mi][j][2] + bx, oy = acc[mi][j][3] + by;
                *reinterpret_cast<float2*>(Y + (size_t)m1 * ldY + col) = make_float2(ox, oy);
                if (STATS) { s0 += ox; q0 += ox * ox; s1 += oy; q1 += oy * oy; }
            }
        }
        if (STATS) {
#pragma unroll
            for (int o = 4; o < 32; o <<= 1) {
                s0 += __shfl_xor_sync(0xffffffffu, s0, o);
                s1 += __shfl_xor_sync(0xffffffffu, s1, o);
                q0 += __shfl_xor_sync(0xffffffffu, q0, o);
                q1 += __shfl_xor_sync(0xffffffffu, q1, o);
            }
            if ((lane >> 2) == 0) {
                atomicAdd(&g_stats[col], s0);
                atomicAdd(&g_stats[col + 1], s1);
                atomicAdd(&g_stats[DD + col], q0);
                atomicAdd(&g_stats[DD + col + 1], q1);
            }
        }
    }
}

// ==================== fused layer-2 tail: mean-agg(P) + R + bias -> log_softmax ====================
__global__ void agg_lsm_kernel(const float* __restrict__ PR, const float* __restrict__ bl2,
                               float* __restrict__ out) {
    int row = blockIdx.x * 8 + (threadIdx.x >> 5);
    int lane = threadIdx.x & 31;
    if (row >= NN) return;
    int beg = g_rowstart[row];
    int cnt = g_deg[row];
    int end = beg + cnt;
    float s0 = 0.f, s1 = 0.f;
    int e = beg;
    for (; e + 2 <= end; e += 2) {
        int sa = g_csrsrc[e], sb2 = g_csrsrc[e + 1];
        const float* pa = PR + (size_t)sa * PRW;
        const float* pb = PR + (size_t)sb2 * PRW;
        if (lane < CC) s0 += pa[lane] + pb[lane];
        if (lane + 32 < CC) s1 += pa[lane + 32] + pb[lane + 32];
    }
    for (; e < end; e++) {
        int src = g_csrsrc[e];
        const float* pr = PR + (size_t)src * PRW;
        if (lane < CC) s0 += pr[lane];
        if (lane + 32 < CC) s1 += pr[lane + 32];
    }
    float inv = 1.0f / (float)(cnt > 0 ? cnt : 1);
    const float* prn = PR + (size_t)row * PRW;
    float v0 = (lane < CC) ? s0 * inv + prn[CC + lane] + bl2[lane] : -INFINITY;
    float v1 = (lane + 32 < CC) ? s1 * inv + prn[CC + lane + 32] + bl2[lane + 32] : -INFINITY;

    float m = fmaxf(v0, v1);
#pragma unroll
    for (int o = 16; o > 0; o >>= 1) m = fmaxf(m, __shfl_xor_sync(0xffffffffu, m, o));
    float s = ((lane < CC) ? expf(v0 - m) : 0.f) + ((lane + 32 < CC) ? expf(v1 - m) : 0.f);
#pragma unroll
    for (int o = 16; o > 0; o >>= 1) s += __shfl_xor_sync(0xffffffffu, s, o);
    float l = m + logf(s);
    float* p = out + (size_t)row * CC;
    if (lane < CC) p[lane] = v0 - l;
    if (lane + 32 < CC) p[lane + 32] = v1 - l;
}

// ==================== launch ====================
extern "C" void kernel_launch(void* const* d_in, const int* in_sizes, int n_in,
                              void* d_out, int out_size) {
    const float* x   = (const float*)d_in[0];
    const void*  ei  = d_in[1];
    const float* Wl0 = (const float*)d_in[2];
    const float* bl0 = (const float*)d_in[3];
    const float* Wr0 = (const float*)d_in[4];
    const float* g0  = (const float*)d_in[5];
    const float* be0 = (const float*)d_in[6];
    const float* Wl1 = (const float*)d_in[7];
    const float* bl1 = (const float*)d_in[8];
    const float* Wr1 = (const float*)d_in[9];
    const float* g1  = (const float*)d_in[10];
    const float* be1 = (const float*)d_in[11];
    const float* Wl2 = (const float*)d_in[12];
    const float* bl2 = (const float*)d_in[13];
    const float* Wr2 = (const float*)d_in[14];
    float* out = (float*)d_out;

    void* p;
    cudaGetSymbolAddress(&p, g_b0);    float* b0p  = (float*)p;
    cudaGetSymbolAddress(&p, g_b1);    float* b1p  = (float*)p;
    cudaGetSymbolAddress(&p, g_pr);    float* prp  = (float*)p;
    cudaGetSymbolAddress(&p, g_aghi);  __nv_bfloat16* aghi = (__nv_bfloat16*)p;
    cudaGetSymbolAddress(&p, g_aglo);  __nv_bfloat16* aglo = (__nv_bfloat16*)p;
    cudaGetSymbolAddress(&p, g_achi);  __nv_bfloat16* achi = (__nv_bfloat16*)p;
    cudaGetSymbolAddress(&p, g_aclo);  __nv_bfloat16* aclo = (__nv_bfloat16*)p;
    cudaGetSymbolAddress(&p, g_w01hi); __nv_bfloat16* w01hi = (__nv_bfloat16*)p;
    cudaGetSymbolAddress(&p, g_w01lo); __nv_bfloat16* w01lo = (__nv_bfloat16*)p;
    cudaGetSymbolAddress(&p, g_w2hi);  __nv_bfloat16* w2hi  = (__nv_bfloat16*)p;
    cudaGetSymbolAddress(&p, g_w2lo);  __nv_bfloat16* w2lo  = (__nv_bfloat16*)p;

    const int SMEM01 = 2 * 128 * STRIDE_B + 2 * 128 * STRIDE_B;
    const int SMEM2  = 2 * 128 * STRIDE_B + 2 * PRW * STRIDE_B;
    cudaFuncSetAttribute((const void*)gemm_mma<128, 2, true>,
                         cudaFuncAttributeMaxDynamicSharedMemorySize, SMEM01);
    cudaFuncSetAttribute((const void*)gemm_mma<PRW, 1, false>,
                         cudaFuncAttributeMaxDynamicSharedMemorySize, SMEM2);

    const int gemm_blocks = (NN + 127) / 128;
    const int agg_blocks = (NN * 32 + 255) / 256;
    const int bnsplit_blocks = (XITEMS + 255) / 256;
    const int prep_items = XITEMS + 2 * 128 * 256 + PRW * 128;

    // CSR build (launches 1-4), prep (5) — launch 6 = agg (ncu -s 5 -c 1 capture)
    initall_kernel<<<(NN + 255) / 256, 256>>>((const int*)ei);
    deg_kernel<<<(EE + 255) / 256, 256>>>(ei);
    scanfused_kernel<<<(NN + 1023) / 1024, 1024>>>();
    scatter_kernel<<<(EE + 255) / 256, 256>>>(ei);
    prep_kernel<<<(prep_items + 255) / 256, 256>>>(x, Wl0, Wr0, Wl1, Wr1, Wl2, Wr2);

    // layer 0
    agg_kernel<<<agg_blocks, 256>>>(x);
    gemm_mma<128, 2, true><<<gemm_blocks, 256, SMEM01>>>(
        aghi, aglo, achi, aclo, w01hi, w01lo, bl0, b0p, DD);
    finalize_kernel<<<1, 128>>>(g0, be0);
    bnsplit_kernel<true><<<bnsplit_blocks, 256>>>(b0p, b1p);

    // layer 1
    agg_kernel<<<agg_blocks, 256>>>(b1p);
    gemm_mma<128, 2, true><<<gemm_blocks, 256, SMEM01>>>(
        aghi, aglo, achi, aclo, w01hi + 128 * 256, w01lo + 128 * 256, bl1, b0p, DD);
    finalize_kernel<<<1, 128>>>(g1, be1);
    bnsplit_kernel<false><<<bnsplit_blocks, 256>>>(b0p, nullptr);

    // layer 2
    gemm_mma<PRW, 1, false><<<gemm_blocks, 256, SMEM2>>>(
        achi, aclo, achi, aclo, w2hi, w2lo, nullptr, prp, PRW);
    agg_lsm_kernel<<<(NN + 7) / 8, 256>>>(prp, bl2, out);
}

// round 16
// speedup vs baseline: 1.1177x; 1.0521x over previous
#include <cuda_runtime.h>
#include <cuda_bf16.h>
#include <math.h>
#include <stdint.h>

#define NN 100000
#define EE 1600000
#define DD 128
#define CC 47
#define PRW 96   // [P(47) | R(47) | pad(2)] width for layer 2

// ==================== scratch (device globals, no allocation) ====================
__device__ int   g_deg[NN];
__device__ int   g_rowstart[NN];
__device__ int   g_cursor[NN];
__device__ int   g_csrsrc[EE];
__device__ float g_b0[(size_t)NN * DD];    // Y0, later Y1 (pre-BN GEMM outputs)
__device__ float g_b1[(size_t)NN * DD];    // h0 = relu(bn0(Y0)) fp32 (for layer-1 agg)
__device__ float g_pr[(size_t)NN * PRW];
__device__ float g_stats[2 * DD];
__device__ float g_scale[DD];
__device__ float g_shift[DD];
__device__ int   g_is64;
__device__ int   g_blockbase;
// split bf16 activation buffers
__device__ __nv_bfloat16 g_aghi[(size_t)NN * DD];   // agg output split
__device__ __nv_bfloat16 g_aglo[(size_t)NN * DD];
__device__ __nv_bfloat16 g_achi[(size_t)NN * DD];   // x-split -> h0-split -> h1-split
__device__ __nv_bfloat16 g_aclo[(size_t)NN * DD];
// W^T images, bf16 hi/lo
__device__ __nv_bfloat16 g_w01hi[2][128 * 256];
__device__ __nv_bfloat16 g_w01lo[2][128 * 256];
__device__ __nv_bfloat16 g_w2hi[PRW * 128];
__device__ __nv_bfloat16 g_w2lo[PRW * 128];

// ==================== PTX helpers (baseline ISA, no 'a' features) ====================
static __device__ __forceinline__ uint32_t smem_u32(const void* p) {
    uint32_t a;
    asm("{ .reg .u64 t; cvta.to.shared.u64 t, %1; cvt.u32.u64 %0, t; }" : "=r"(a) : "l"(p));
    return a;
}
#define LDSM4(r, a) \
    asm volatile("ldmatrix.sync.aligned.m8n8.x4.shared.b16 {%0,%1,%2,%3}, [%4];" \
                 : "=r"((r)[0]), "=r"((r)[1]), "=r"((r)[2]), "=r"((r)[3]) : "r"(a))
#define MMA16816(d, a, b0, b1) \
    asm volatile("mma.sync.aligned.m16n8k16.row.col.f32.bf16.bf16.f32 " \
                 "{%0,%1,%2,%3}, {%4,%5,%6,%7}, {%8,%9}, {%0,%1,%2,%3};" \
                 : "+f"((d)[0]), "+f"((d)[1]), "+f"((d)[2]), "+f"((d)[3]) \
                 : "r"((a)[0]), "r"((a)[1]), "r"((a)[2]), "r"((a)[3]), "r"(b0), "r"(b1))

__device__ __forceinline__ int edge_val(const void* ei, int is64, size_t idx) {
    if (is64) return (int)((const long long*)ei)[idx];
    return ((const int*)ei)[idx];
}

static __device__ __forceinline__ void split2(float4 v, uint2& hp, uint2& lp) {
    __nv_bfloat16 hx = __float2bfloat16_rn(v.x);
    __nv_bfloat16 hy = __float2bfloat16_rn(v.y);
    __nv_bfloat16 hz = __float2bfloat16_rn(v.z);
    __nv_bfloat16 hw = __float2bfloat16_rn(v.w);
    __nv_bfloat16 lx = __float2bfloat16_rn(v.x - __bfloat162float(hx));
    __nv_bfloat16 ly = __float2bfloat16_rn(v.y - __bfloat162float(hy));
    __nv_bfloat16 lz = __float2bfloat16_rn(v.z - __bfloat162float(hz));
    __nv_bfloat16 lw = __float2bfloat16_rn(v.w - __bfloat162float(hw));
    hp.x = (uint32_t)__bfloat16_as_ushort(hx) | ((uint32_t)__bfloat16_as_ushort(hy) << 16);
    hp.y = (uint32_t)__bfloat16_as_ushort(hz) | ((uint32_t)__bfloat16_as_ushort(hw) << 16);
    lp.x = (uint32_t)__bfloat16_as_ushort(lx) | ((uint32_t)__bfloat16_as_ushort(ly) << 16);
    lp.y = (uint32_t)__bfloat16_as_ushort(lz) | ((uint32_t)__bfloat16_as_ushort(lw) << 16);
}

// ==================== init: probe + zero deg/stats/blockbase ====================
__global__ void initall_kernel(const int* __restrict__ ei32) {
    int i = blockIdx.x * blockDim.x + threadIdx.x;
    if (i < NN) g_deg[i] = 0;
    if (i < 2 * DD) g_stats[i] = 0.f;
    if (i == 0) {
        g_blockbase = 0;
        int nz = 0;
        for (int k = 0; k < 512; k++) nz += (ei32[2 * k + 1] != 0);
        g_is64 = (nz == 0) ? 1 : 0;
    }
}

// ==================== CSR build ====================
__global__ void deg_kernel(const void* __restrict__ ei) {
    int e = blockIdx.x * blockDim.x + threadIdx.x;
    int is64 = g_is64;
    if (e < EE) atomicAdd(&g_deg[edge_val(ei, is64, (size_t)EE + e)], 1);
}

// fused scan: per-block scan + atomic block base (ranges contiguous per node; order-free)
__global__ void scanfused_kernel() {
    __shared__ int wsum[32];
    __shared__ int sbase;
    int t = threadIdx.x;
    int lane = t & 31, wid = t >> 5;
    int i = blockIdx.x * 1024 + t;
    int v = (i < NN) ? g_deg[i] : 0;
    int x = v;
#pragma unroll
    for (int o = 1; o < 32; o <<= 1) {
        int u = __shfl_up_sync(0xffffffffu, x, o);
        if (lane >= o) x += u;
    }
    if (lane == 31) wsum[wid] = x;
    __syncthreads();
    if (wid == 0) {
        int s = wsum[lane];
        int y = s;
#pragma unroll
        for (int o = 1; o < 32; o <<= 1) {
            int u = __shfl_up_sync(0xffffffffu, y, o);
            if (lane >= o) y += u;
        }
        wsum[lane] = y - s;
        if (lane == 31) sbase = atomicAdd(&g_blockbase, y);
    }
    __syncthreads();
    int excl = x - v + wsum[wid] + sbase;
    if (i < NN) {
        g_rowstart[i] = excl;
        g_cursor[i] = excl;
    }
}

__global__ void scatter_kernel(const void* __restrict__ ei) {
    int e = blockIdx.x * blockDim.x + threadIdx.x;
    int is64 = g_is64;
    if (e < EE) {
        int d = edge_val(ei, is64, (size_t)EE + e);
        int s = edge_val(ei, is64, (size_t)e);
        int p = atomicAdd(&g_cursor[d], 1);
        g_csrsrc[p] = s;
    }
}

// ==================== prep: weight conversion + x split (one kernel) ====================
#define XITEMS (NN * DD / 4)
__global__ void prep_kernel(const float* __restrict__ x,
                            const float* __restrict__ Wl0, const float* __restrict__ Wr0,
                            const float* __restrict__ Wl1, const float* __restrict__ Wr1,
                            const float* __restrict__ Wl2, const float* __restrict__ Wr2) {
    int idx = blockIdx.x * blockDim.x + threadIdx.x;
    if (idx < XITEMS) {
        float4 v = __ldg(reinterpret_cast<const float4*>(x) + idx);
        uint2 hp, lp;
        split2(v, hp, lp);
        reinterpret_cast<uint2*>(g_achi)[idx] = hp;
        reinterpret_cast<uint2*>(g_aclo)[idx] = lp;
        return;
    }
    int r = idx - XITEMS;
    if (r < 2 * 128 * 256) {
        int layer = r >> 15;
        int q = r & 32767;
        int n = q >> 8;
        int k = q & 255;
        const float* Wl = layer ? Wl1 : Wl0;
        const float* Wr = layer ? Wr1 : Wr0;
        float v = (k < 128) ? Wl[k * 128 + n] : Wr[(k - 128) * 128 + n];
        __nv_bfloat16 hi = __float2bfloat16_rn(v);
        __nv_bfloat16 lo = __float2bfloat16_rn(v - __bfloat162float(hi));
        g_w01hi[layer][n * 256 + k] = hi;
        g_w01lo[layer][n * 256 + k] = lo;
        return;
    }
    r -= 2 * 128 * 256;
    if (r < PRW * 128) {
        int n = r >> 7;
        int k = r & 127;
        float v = 0.f;
        if (n < CC) v = Wl2[k * CC + n];
        else if (n < 2 * CC) v = Wr2[k * CC + (n - CC)];
        __nv_bfloat16 hi = __float2bfloat16_rn(v);
        __nv_bfloat16 lo = __float2bfloat16_rn(v - __bfloat162float(hi));
        g_w2hi[n * 128 + k] = hi;
        g_w2lo[n * 128 + k] = lo;
    }
}

// ==================== BN finalize: stats -> scale/shift, re-zero stats ====================
__global__ void finalize_kernel(const float* __restrict__ g, const float* __restrict__ b) {
    int c = threadIdx.x;
    if (c < DD) {
        float mu = g_stats[c] * (1.0f / NN);
        float var = g_stats[DD + c] * (1.0f / NN) - mu * mu;
        float sc = rsqrtf(var + 1e-5f) * g[c];
        g_scale[c] = sc;
        g_shift[c] = b[c] - mu * sc;
        g_stats[c] = 0.f;
        g_stats[DD + c] = 0.f;
    }
}

// ==================== bnsplit: Y -> (optional fp32 H) + split bf16 pair ====================
template <bool F32OUT>
__global__ void bnsplit_kernel(const float* __restrict__ Y, float* __restrict__ H) {
    int idx = blockIdx.x * blockDim.x + threadIdx.x;
    if (idx >= XITEMS) return;
    int q = idx & 31;
    float4 v = __ldg(reinterpret_cast<const float4*>(Y) + idx);
    float4 s4 = *reinterpret_cast<const float4*>(g_scale + q * 4);
    float4 h4 = *reinterpret_cast<const float4*>(g_shift + q * 4);
    v.x = fmaxf(fmaf(v.x, s4.x, h4.x), 0.f);
    v.y = fmaxf(fmaf(v.y, s4.y, h4.y), 0.f);
    v.z = fmaxf(fmaf(v.z, s4.z, h4.z), 0.f);
    v.w = fmaxf(fmaf(v.w, s4.w, h4.w), 0.f);
    if (F32OUT) reinterpret_cast<float4*>(H)[idx] = v;
    uint2 hp, lp;
    split2(v, hp, lp);
    reinterpret_cast<uint2*>(g_achi)[idx] = hp;
    reinterpret_cast<uint2*>(g_aclo)[idx] = lp;
}

// ==================== mean aggregation (warp per node), split-bf16 output ====================
__global__ void agg_kernel(const float* __restrict__ X) {
    int warp = (blockIdx.x * blockDim.x + threadIdx.x) >> 5;
    int lane = threadIdx.x & 31;
    if (warp >= NN) return;
    int beg = g_rowstart[warp];
    int cnt = g_deg[warp];
    int end = beg + cnt;
    float4 acc = make_float4(0.f, 0.f, 0.f, 0.f);
    int e = beg;
    for (; e + 4 <= end; e += 4) {
        int s0 = g_csrsrc[e + 0];
        int s1 = g_csrsrc[e + 1];
        int s2 = g_csrsrc[e + 2];
        int s3 = g_csrsrc[e + 3];
        float4 v0 = *reinterpret_cast<const float4*>(X + (size_t)s0 * DD + lane * 4);
        float4 v1 = *reinterpret_cast<const float4*>(X + (size_t)s1 * DD + lane * 4);
        float4 v2 = *reinterpret_cast<const float4*>(X + (size_t)s2 * DD + lane * 4);
        float4 v3 = *reinterpret_cast<const float4*>(X + (size_t)s3 * DD + lane * 4);
        acc.x += (v0.x + v1.x) + (v2.x + v3.x);
        acc.y += (v0.y + v1.y) + (v2.y + v3.y);
        acc.z += (v0.z + v1.z) + (v2.z + v3.z);
        acc.w += (v0.w + v1.w) + (v2.w + v3.w);
    }
    for (; e < end; e++) {
        int s = g_csrsrc[e];
        float4 v = *reinterpret_cast<const float4*>(X + (size_t)s * DD + lane * 4);
        acc.x += v.x; acc.y += v.y; acc.z += v.z; acc.w += v.w;
    }
    float inv = 1.0f / (float)(cnt > 0 ? cnt : 1);
    acc.x *= inv; acc.y *= inv; acc.z *= inv; acc.w *= inv;
    uint2 hp, lp;
    split2(acc, hp, lp);
    reinterpret_cast<uint2*>(g_aghi)[(size_t)warp * 32 + lane] = hp;
    reinterpret_cast<uint2*>(g_aglo)[(size_t)warp * 32 + lane] = lp;
}

// ==================== HMMA split-bf16 GEMM, 2 CTAs/SM (two-phase A buffer) ====================
// Per K-chunk: phase 1: A=Ahi, terms Ahi@Whi + Ahi@Wlo; phase 2: A=Alo, term Alo@Whi.
#define STRIDE_B 272
template <int NT, int NCHUNK, bool STATS>
__global__ void __launch_bounds__(256, 2)
gemm_mma(const __nv_bfloat16* __restrict__ A0hi, const __nv_bfloat16* __restrict__ A0lo,
         const __nv_bfloat16* __restrict__ A1hi, const __nv_bfloat16* __restrict__ A1lo,
         const __nv_bfloat16* __restrict__ Whi, const __nv_bfloat16* __restrict__ Wlo,
         const float* __restrict__ bias, float* __restrict__ Y, int ldY) {
    extern __shared__ char smem[];
    constexpr int ABUF = 0;
    constexpr int WHI = 128 * STRIDE_B;
    constexpr int WLO = WHI + NT * STRIDE_B;
    constexpr int NB4 = NT / 32;
    constexpr int NTJ = NT / 16;

    const uint32_t sb = smem_u32(smem);
    const int tid = threadIdx.x;
    const int wid = tid >> 5, lane = tid & 31;
    const int warp_m = wid & 3, warp_n = wid >> 2;
    const int nbase = blockIdx.x * 128;

    float acc[2][NTJ][4];
#pragma unroll
    for (int i = 0; i < 2; i++)
#pragma unroll
        for (int j = 0; j < NTJ; j++)
#pragma unroll
            for (int q = 0; q < 4; q++) acc[i][j][q] = 0.f;

    const int lt = lane >> 3, lrow = lane & 7;
    const int a_m = warp_m * 32 + lrow + ((lt & 1) << 3);
    const int a_k = (lt >> 1) << 3;
    const int b_n = warp_n * (NT / 2) + lrow + ((lt >> 1) << 3);
    const int b_k = (lt & 1) << 3;

#pragma unroll 1
    for (int c = 0; c < NCHUNK; c++) {
        const __nv_bfloat16* Ahi = (NCHUNK == 2 && c == 1) ? A1hi : A0hi;
        const __nv_bfloat16* Alo = (NCHUNK == 2 && c == 1) ? A1lo : A0lo;

        // W chunk (hi+lo) — stays resident across both phases
        for (int i = tid; i < NT * 16; i += 256) {
            int n = i >> 4, u4 = i & 15;
            size_t gofs = (size_t)n * (NCHUNK * 128) + c * 128 + u4 * 8;
            int off = n * STRIDE_B + u4 * 16;
            *reinterpret_cast<uint4*>(smem + WHI + off) =
                *reinterpret_cast<const uint4*>(Whi + gofs);
            *reinterpret_cast<uint4*>(smem + WLO + off) =
                *reinterpret_cast<const uint4*>(Wlo + gofs);
        }
        // phase 1: A = Ahi
        for (int i = tid; i < 2048; i += 256) {
            int r = i >> 4, u = i & 15;
            int n = nbase + r;
            if (n >= NN) n = NN - 1;
            uint4 h = __ldg(reinterpret_cast<const uint4*>(Ahi + (size_t)n * DD) + u);
            *reinterpret_cast<uint4*>(smem + ABUF + r * STRIDE_B + u * 16) = h;
        }
        __syncthreads();

#pragma unroll
        for (int ks = 0; ks < 8; ks++) {
            const int kb = ks * 16;
            uint32_t af[2][4], bhi[NB4][4], blo[NB4][4];
#pragma unroll
            for (int mi = 0; mi < 2; mi++) {
                uint32_t ad = sb + ABUF + (a_m + mi * 16) * STRIDE_B + (kb + a_k) * 2;
                LDSM4(af[mi], ad);
            }
#pragma unroll
            for (int g = 0; g < NB4; g++) {
                uint32_t bd = sb + WHI + (b_n + g * 16) * STRIDE_B + (kb + b_k) * 2;
                LDSM4(bhi[g], bd);
                LDSM4(blo[g], bd + (WLO - WHI));
            }
#pragma unroll
            for (int mi = 0; mi < 2; mi++)
#pragma unroll
                for (int g = 0; g < NB4; g++)
#pragma unroll
                    for (int h = 0; h < 2; h++) {
                        int j = g * 2 + h;
                        MMA16816(acc[mi][j], af[mi], bhi[g][h * 2], bhi[g][h * 2 + 1]);
                        MMA16816(acc[mi][j], af[mi], blo[g][h * 2], blo[g][h * 2 + 1]);
                    }
        }
        __syncthreads();

        // phase 2: A = Alo (same buffer), term Alo@Whi
        for (int i = tid; i < 2048; i += 256) {
            int r = i >> 4, u = i & 15;
            int n = nbase + r;
            if (n >= NN) n = NN - 1;
            uint4 l = __ldg(reinterpret_cast<const uint4*>(Alo + (size_t)n * DD) + u);
            *reinterpret_cast<uint4*>(smem + ABUF + r * STRIDE_B + u * 16) = l;
        }
        __syncthreads();

#pragma unroll
        for (int ks = 0; ks < 8; ks++) {
            const int kb = ks * 16;
            uint32_t af[2][4], bhi[NB4][4];
#pragma unroll
            for (int mi = 0; mi < 2; mi++) {
                uint32_t ad = sb + ABUF + (a_m + mi * 16) * STRIDE_B + (kb + a_k) * 2;
                LDSM4(af[mi], ad);
            }
#pragma unroll
            for (int g = 0; g < NB4; g++) {
                uint32_t bd = sb + WHI + (b_n + g * 16) * STRIDE_B + (kb + b_k) * 2;
                LDSM4(bhi[g], bd);
            }
#pragma unroll
            for (int mi = 0; mi < 2; mi++)
#pragma unroll
                for (int g = 0; g < NB4; g++)
#pragma unroll
                    for (int h = 0; h < 2; h++) {
                        int j = g * 2 + h;
                        MMA16816(acc[mi][j], af[mi], bhi[g][h * 2], bhi[g][h * 2 + 1]);
                    }
        }
        __syncthreads();
    }

    // ---- epilogue: bias + store + optional column stats ----
    const int mrow = nbase + warp_m * 32 + (lane >> 2);
#pragma unroll
    for (int j = 0; j < NTJ; j++) {
        int col = warp_n * (NT / 2) + j * 8 + (lane & 3) * 2;
        float bx = bias ? bias[col] : 0.f;
        float by = bias ? bias[col + 1] : 0.f;
        float s0 = 0.f, s1 = 0.f, q0 = 0.f, q1 = 0.f;
#pragma unroll
        for (int mi = 0; mi < 2; mi++) {
            int m0 = mrow + mi * 16;
            if (m0 < NN) {
                float ox = acc[mi][j][0] + bx, oy = acc[mi][j][1] + by;
                *reinterpret_cast<float2*>(Y + (size_t)m0 * ldY + col) = make_float2(ox, oy);
                if (STATS) { s0 += ox; q0 += ox * ox; s1 += oy; q1 += oy * oy; }
            }
            int m1 = m0 + 8;
            if (m1 < NN) {
                float ox = acc[mi][j][2] + bx, oy = acc[mi][j][3] + by;
                *reinterpret_cast<float2*>(Y + (size_t)m1 * ldY + col) = make_float2(ox, oy);
                if (STATS) { s0 += ox; q0 += ox * ox; s1 += oy; q1 += oy * oy; }
            }
        }
        if (STATS) {
#pragma unroll
            for (int o = 4; o < 32; o <<= 1) {
                s0 += __shfl_xor_sync(0xffffffffu, s0, o);
                s1 += __shfl_xor_sync(0xffffffffu, s1, o);
                q0 += __shfl_xor_sync(0xffffffffu, q0, o);
                q1 += __shfl_xor_sync(0xffffffffu, q1, o);
            }
            if ((lane >> 2) == 0) {
                atomicAdd(&g_stats[col], s0);
                atomicAdd(&g_stats[col + 1], s1);
                atomicAdd(&g_stats[DD + col], q0);
                atomicAdd(&g_stats[DD + col + 1], q1);
            }
        }
    }
}

// ==================== fused layer-2 tail: mean-agg(P) + R + bias -> log_softmax ====================
__global__ void agg_lsm_kernel(const float* __restrict__ PR, const float* __restrict__ bl2,
                               float* __restrict__ out) {
    int row = blockIdx.x * 8 + (threadIdx.x >> 5);
    int lane = threadIdx.x & 31;
    if (row >= NN) return;
    int beg = g_rowstart[row];
    int cnt = g_deg[row];
    int end = beg + cnt;
    float s0 = 0.f, s1 = 0.f;
    int e = beg;
    for (; e + 2 <= end; e += 2) {
        int sa = g_csrsrc[e], sb2 = g_csrsrc[e + 1];
        const float* pa = PR + (size_t)sa * PRW;
        const float* pb = PR + (size_t)sb2 * PRW;
        if (lane < CC) s0 += pa[lane] + pb[lane];
        if (lane + 32 < CC) s1 += pa[lane + 32] + pb[lane + 32];
    }
    for (; e < end; e++) {
        int src = g_csrsrc[e];
        const float* pr = PR + (size_t)src * PRW;
        if (lane < CC) s0 += pr[lane];
        if (lane + 32 < CC) s1 += pr[lane + 32];
    }
    float inv = 1.0f / (float)(cnt > 0 ? cnt : 1);
    const float* prn = PR + (size_t)row * PRW;
    float v0 = (lane < CC) ? s0 * inv + prn[CC + lane] + bl2[lane] : -INFINITY;
    float v1 = (lane + 32 < CC) ? s1 * inv + prn[CC + lane + 32] + bl2[lane + 32] : -INFINITY;

    float m = fmaxf(v0, v1);
#pragma unroll
    for (int o = 16; o > 0; o >>= 1) m = fmaxf(m, __shfl_xor_sync(0xffffffffu, m, o));
    float s = ((lane < CC) ? expf(v0 - m) : 0.f) + ((lane + 32 < CC) ? expf(v1 - m) : 0.f);
#pragma unroll
    for (int o = 16; o > 0; o >>= 1) s += __shfl_xor_sync(0xffffffffu, s, o);
    float l = m + logf(s);
    float* p = out + (size_t)row * CC;
    if (lane < CC) p[lane] = v0 - l;
    if (lane + 32 < CC) p[lane + 32] = v1 - l;
}

// ==================== launch ====================
extern "C" void kernel_launch(void* const* d_in, const int* in_sizes, int n_in,
                              void* d_out, int out_size) {
    const float* x   = (const float*)d_in[0];
    const void*  ei  = d_in[1];
    const float* Wl0 = (const float*)d_in[2];
    const float* bl0 = (const float*)d_in[3];
    const float* Wr0 = (const float*)d_in[4];
    const float* g0  = (const float*)d_in[5];
    const float* be0 = (const float*)d_in[6];
    const float* Wl1 = (const float*)d_in[7];
    const float* bl1 = (const float*)d_in[8];
    const float* Wr1 = (const float*)d_in[9];
    const float* g1  = (const float*)d_in[10];
    const float* be1 = (const float*)d_in[11];
    const float* Wl2 = (const float*)d_in[12];
    const float* bl2 = (const float*)d_in[13];
    const float* Wr2 = (const float*)d_in[14];
    float* out = (float*)d_out;

    void* p;
    cudaGetSymbolAddress(&p, g_b0);    float* b0p  = (float*)p;
    cudaGetSymbolAddress(&p, g_b1);    float* b1p  = (float*)p;
    cudaGetSymbolAddress(&p, g_pr);    float* prp  = (float*)p;
    cudaGetSymbolAddress(&p, g_aghi);  __nv_bfloat16* aghi = (__nv_bfloat16*)p;
    cudaGetSymbolAddress(&p, g_aglo);  __nv_bfloat16* aglo = (__nv_bfloat16*)p;
    cudaGetSymbolAddress(&p, g_achi);  __nv_bfloat16* achi = (__nv_bfloat16*)p;
    cudaGetSymbolAddress(&p, g_aclo);  __nv_bfloat16* aclo = (__nv_bfloat16*)p;
    cudaGetSymbolAddress(&p, g_w01hi); __nv_bfloat16* w01hi = (__nv_bfloat16*)p;
    cudaGetSymbolAddress(&p, g_w01lo); __nv_bfloat16* w01lo = (__nv_bfloat16*)p;
    cudaGetSymbolAddress(&p, g_w2hi);  __nv_bfloat16* w2hi  = (__nv_bfloat16*)p;
    cudaGetSymbolAddress(&p, g_w2lo);  __nv_bfloat16* w2lo  = (__nv_bfloat16*)p;

    const int SMEM01 = 128 * STRIDE_B + 2 * 128 * STRIDE_B;   // 104448 -> 2 CTAs/SM
    const int SMEM2  = 128 * STRIDE_B + 2 * PRW * STRIDE_B;   // 87040  -> 2 CTAs/SM
    cudaFuncSetAttribute((const void*)gemm_mma<128, 2, true>,
                         cudaFuncAttributeMaxDynamicSharedMemorySize, SMEM01);
    cudaFuncSetAttribute((const void*)gemm_mma<PRW, 1, false>,
                         cudaFuncAttributeMaxDynamicSharedMemorySize, SMEM2);

    const int gemm_blocks = (NN + 127) / 128;
    const int agg_blocks = (NN * 32 + 255) / 256;
    const int bnsplit_blocks = (XITEMS + 255) / 256;
    const int prep_items = XITEMS + 2 * 128 * 256 + PRW * 128;

    // CSR build + prep
    initall_kernel<<<(NN + 255) / 256, 256>>>((const int*)ei);
    deg_kernel<<<(EE + 255) / 256, 256>>>(ei);
    scanfused_kernel<<<(NN + 1023) / 1024, 1024>>>();
    scatter_kernel<<<(EE + 255) / 256, 256>>>(ei);
    prep_kernel<<<(prep_items + 255) / 256, 256>>>(x, Wl0, Wr0, Wl1, Wr1, Wl2, Wr2);

    // layer 0
    agg_kernel<<<agg_blocks, 256>>>(x);
    gemm_mma<128, 2, true><<<gemm_blocks, 256, SMEM01>>>(
        aghi, aglo, achi, aclo, w01hi, w01lo, bl0, b0p, DD);
    finalize_kernel<<<1, 128>>>(g0, be0);
    bnsplit_kernel<true><<<bnsplit_blocks, 256>>>(b0p, b1p);

    // layer 1
    agg_kernel<<<agg_blocks, 256>>>(b1p);
    gemm_mma<128, 2, true><<<gemm_blocks, 256, SMEM01>>>(
        aghi, aglo, achi, aclo, w01hi + 128 * 256, w01lo + 128 * 256, bl1, b0p, DD);
    finalize_kernel<<<1, 128>>>(g1, be1);
    bnsplit_kernel<false><<<bnsplit_blocks, 256>>>(b0p, nullptr);

    // layer 2
    gemm_mma<PRW, 1, false><<<gemm_blocks, 256, SMEM2>>>(
        achi, aclo, achi, aclo, w2hi, w2lo, nullptr, prp, PRW);
    agg_lsm_kernel<<<(NN + 7) / 8, 256>>>(prp, bl2, out);
}